// round 7
// baseline (speedup 1.0000x reference)
#include <cuda_runtime.h>
#include <cstdint>

#define N_NODES 20000
#define N_EDGES 320000
#define E_TOT   (N_EDGES + N_NODES)
#define NUM_GRAPHS 64
#define OUT_CH 200

// ---------------- scratch (static device globals; no runtime alloc) ------------
__device__ float g_h[(size_t)N_NODES * 512];    // GEMM output (per-layer transformed feats)
__device__ float g_hin[(size_t)N_NODES * 512];  // activated layer input / aggregate output
__device__ float g_as[(size_t)N_NODES * 4];
__device__ float g_ad[(size_t)N_NODES * 4];
__device__ int   g_rowp[N_NODES + 1];
__device__ int   g_cnt[N_NODES];
__device__ int   g_srcs[E_TOT];
__device__ float g_pool[NUM_GRAPHS * 128];
__device__ int   g_gstart[NUM_GRAPHS + 1];

// ---------------- helpers ----------------
__device__ __forceinline__ unsigned fenc(float f) {
    unsigned u = __float_as_uint(f);
    return (u & 0x80000000u) ? ~u : (u | 0x80000000u);
}
__device__ __forceinline__ float fdec(unsigned e) {
    unsigned u = (e & 0x80000000u) ? (e & 0x7fffffffu) : ~e;
    return __uint_as_float(u);
}

// ---------------- CSR build ----------------
__global__ void k_init_counts() {
    int i = blockIdx.x * blockDim.x + threadIdx.x;
    if (i < N_NODES) g_cnt[i] = 1;  // self loop
}
__global__ void k_count_edges(const int* __restrict__ dst) {
    int i = blockIdx.x * blockDim.x + threadIdx.x;
    if (i < N_EDGES) atomicAdd(&g_cnt[dst[i]], 1);
}
__global__ void k_scan() {
    __shared__ int part[1024];
    const int tid = threadIdx.x;
    const int n = N_NODES;
    const int CH = (n + 1023) / 1024;
    const int base = tid * CH;
    int s = 0;
    for (int i = 0; i < CH; i++) {
        int idx = base + i;
        if (idx < n) s += g_cnt[idx];
    }
    part[tid] = s;
    __syncthreads();
    for (int off = 1; off < 1024; off <<= 1) {
        int v = 0;
        if (tid >= off) v = part[tid - off];
        __syncthreads();
        if (tid >= off) part[tid] += v;
        __syncthreads();
    }
    int ex = (tid == 0) ? 0 : part[tid - 1];
    for (int i = 0; i < CH; i++) {
        int idx = base + i;
        if (idx < n) { g_rowp[idx] = ex; ex += g_cnt[idx]; }
    }
    if (tid == 1023) g_rowp[n] = part[1023];
}
__global__ void k_init_self() {
    int i = blockIdx.x * blockDim.x + threadIdx.x;
    if (i < N_NODES) {
        int r = g_rowp[i];
        g_srcs[r] = i;     // self loop first
        g_cnt[i] = r + 1;  // scatter cursor
    }
}
__global__ void k_scatter(const int* __restrict__ src, const int* __restrict__ dst) {
    int i = blockIdx.x * blockDim.x + threadIdx.x;
    if (i < N_EDGES) {
        int d = dst[i];
        int p = atomicAdd(&g_cnt[d], 1);
        g_srcs[p] = src[i];
    }
}

// ---------------- SGEMM: C[M,N] = A[M,K] @ B[K,N]; N%128==0, K%16==0 ----------------
__global__ __launch_bounds__(256) void k_sgemm(const float* __restrict__ A,
                                               const float* __restrict__ B,
                                               float* __restrict__ C,
                                               int M, int N, int K) {
    constexpr int BM = 128, BN = 128, BK = 16, TM = 8, TN = 8;
    __shared__ float As[BK][BM];
    __shared__ float Bs[BK][BN];
    const int tid = threadIdx.x;
    const int tr = tid / 16;
    const int tc = tid % 16;
    const int row0 = blockIdx.y * BM;
    const int col0 = blockIdx.x * BN;

    const int ar = tid / 4;          // 0..63
    const int ac = (tid % 4) * 4;    // 0,4,8,12
    const int br = tid / 32;         // 0..7
    const int bc = (tid % 32) * 4;   // 0..124

    float acc[TM][TN];
#pragma unroll
    for (int i = 0; i < TM; i++)
#pragma unroll
        for (int j = 0; j < TN; j++) acc[i][j] = 0.f;

    for (int k0 = 0; k0 < K; k0 += BK) {
#pragma unroll
        for (int i = 0; i < 2; i++) {
            int r = row0 + ar + i * 64;
            float4 v = make_float4(0.f, 0.f, 0.f, 0.f);
            if (r < M) v = *(const float4*)(A + (size_t)r * K + k0 + ac);
            As[ac + 0][ar + i * 64] = v.x;
            As[ac + 1][ar + i * 64] = v.y;
            As[ac + 2][ar + i * 64] = v.z;
            As[ac + 3][ar + i * 64] = v.w;
        }
#pragma unroll
        for (int i = 0; i < 2; i++) {
            int r = k0 + br + i * 8;
            *(float4*)&Bs[br + i * 8][bc] = *(const float4*)(B + (size_t)r * N + col0 + bc);
        }
        __syncthreads();
#pragma unroll
        for (int kk = 0; kk < BK; kk++) {
            float a[TM], b[TN];
#pragma unroll
            for (int i = 0; i < TM; i++) a[i] = As[kk][tr * TM + i];
#pragma unroll
            for (int j = 0; j < TN; j++) b[j] = Bs[kk][tc * TN + j];
#pragma unroll
            for (int i = 0; i < TM; i++)
#pragma unroll
                for (int j = 0; j < TN; j++) acc[i][j] += a[i] * b[j];
        }
        __syncthreads();
    }
#pragma unroll
    for (int i = 0; i < TM; i++) {
        int r = row0 + tr * TM + i;
        if (r < M) {
#pragma unroll
            for (int j = 0; j < TN; j += 4) {
                *(float4*)(C + (size_t)r * N + col0 + tc * TN + j) =
                    make_float4(acc[i][j], acc[i][j + 1], acc[i][j + 2], acc[i][j + 3]);
            }
        }
    }
}

// ---------------- alpha_s / alpha_d : one warp per (node, head), C=128 ----------------
__global__ void k_alpha(const float* __restrict__ h, const float* __restrict__ a_src,
                        const float* __restrict__ a_dst, int N, int H) {
    int w = (blockIdx.x * blockDim.x + threadIdx.x) >> 5;
    int lane = threadIdx.x & 31;
    if (w >= N * H) return;
    int n = w / H, hd = w % H;
    const float* hp = h + (size_t)n * H * 128 + hd * 128;
    float4 v = *(const float4*)(hp + lane * 4);
    float4 s = *(const float4*)(a_src + hd * 128 + lane * 4);
    float4 d = *(const float4*)(a_dst + hd * 128 + lane * 4);
    float ss = v.x * s.x + v.y * s.y + v.z * s.z + v.w * s.w;
    float dd = v.x * d.x + v.y * d.y + v.z * d.z + v.w * d.w;
#pragma unroll
    for (int o = 16; o; o >>= 1) {
        ss += __shfl_down_sync(0xffffffffu, ss, o);
        dd += __shfl_down_sync(0xffffffffu, dd, o);
    }
    if (lane == 0) { g_as[w] = ss; g_ad[w] = dd; }
}

// ---------------- per-node softmax + weighted aggregation (block per node) ----------------
template <int H>
__global__ __launch_bounds__(128) void k_aggregate(
    const float* __restrict__ hft,   // [N, H*128]
    const float* __restrict__ bias, float* __restrict__ out) {
    constexpr int OUTD = H * 128;
    constexpr int CPT = OUTD / 128;   // channels per thread
    const int n = blockIdx.x;
    const int tid = threadIdx.x;
    const int r0 = g_rowp[n];
    const int deg = g_rowp[n + 1] - r0;

    __shared__ unsigned s_maxe[H];
    __shared__ float s_sum[H];
    __shared__ float s_adv[H];
    __shared__ float s_m[H];
    __shared__ float s_den[H];
    __shared__ float s_w[64 * H];
    __shared__ int s_src[64];

    if (tid < H) {
        s_maxe[tid] = 0u;
        s_sum[tid] = 0.f;
        s_adv[tid] = g_ad[(size_t)n * H + tid];
    }
    __syncthreads();

    // phase 1: per-head max of leaky_relu(as[src]+ad[n])
    {
        float lm[H];
#pragma unroll
        for (int h = 0; h < H; h++) lm[h] = -3.0e38f;
        for (int j = tid; j < deg; j += 128) {
            int s = g_srcs[r0 + j];
#pragma unroll
            for (int h = 0; h < H; h++) {
                float e = g_as[(size_t)s * H + h] + s_adv[h];
                e = e > 0.f ? e : 0.2f * e;
                lm[h] = fmaxf(lm[h], e);
            }
        }
#pragma unroll
        for (int h = 0; h < H; h++) atomicMax(&s_maxe[h], fenc(lm[h]));
    }
    __syncthreads();
    if (tid < H) s_m[tid] = fdec(s_maxe[tid]);
    __syncthreads();

    // phase 2: per-head sum of exp(e - m)
    {
        float ls[H];
#pragma unroll
        for (int h = 0; h < H; h++) ls[h] = 0.f;
        for (int j = tid; j < deg; j += 128) {
            int s = g_srcs[r0 + j];
#pragma unroll
            for (int h = 0; h < H; h++) {
                float e = g_as[(size_t)s * H + h] + s_adv[h];
                e = e > 0.f ? e : 0.2f * e;
                ls[h] += expf(e - s_m[h]);
            }
        }
#pragma unroll
        for (int h = 0; h < H; h++)
            if (ls[h] != 0.f) atomicAdd(&s_sum[h], ls[h]);
    }
    __syncthreads();
    if (tid < H) s_den[tid] = s_sum[tid] + 1e-16f;
    __syncthreads();

    // phase 3: chunked weighted gather of h[src]
    const int c0 = tid * CPT;
    const int myh = c0 >> 7;
    float acc[CPT];
#pragma unroll
    for (int i = 0; i < CPT; i++) acc[i] = 0.f;

    for (int base = 0; base < deg; base += 64) {
        int cn = min(64, deg - base);
        __syncthreads();
        if (tid < cn) {
            int s = g_srcs[r0 + base + tid];
            s_src[tid] = s;
#pragma unroll
            for (int h = 0; h < H; h++) {
                float e = g_as[(size_t)s * H + h] + s_adv[h];
                e = e > 0.f ? e : 0.2f * e;
                s_w[tid * H + h] = expf(e - s_m[h]) / s_den[h];
            }
        }
        __syncthreads();
        for (int j = 0; j < cn; j++) {
            int s = s_src[j];
            float coef = s_w[j * H + myh];
            const float* hp = hft + (size_t)s * OUTD + c0;
            if (CPT == 4) {
                float4 v = *(const float4*)hp;
                acc[0] += coef * v.x;
                acc[1] += coef * v.y;
                acc[2] += coef * v.z;
                acc[3] += coef * v.w;
            } else {
                acc[0] += coef * hp[0];
            }
        }
    }
#pragma unroll
    for (int i = 0; i < CPT; i++) {
        float v = acc[i] + bias[c0 + i];
        v = v > 0.f ? v : expm1f(v);   // ELU
        out[(size_t)n * OUTD + c0 + i] = v;
    }
}

// ---------------- pooling / FC ----------------
__global__ void k_gbounds(const int* __restrict__ batch) {
    int g = blockIdx.x * blockDim.x + threadIdx.x;
    const int N = N_NODES, G = NUM_GRAPHS;
    if (g > G) return;
    if (g == G) { g_gstart[G] = N; return; }
    int lo = 0, hi = N;
    while (lo < hi) {
        int mid = (lo + hi) >> 1;
        if (batch[mid] < g) lo = mid + 1;
        else hi = mid;
    }
    g_gstart[g] = lo;
}
__global__ void k_pool(const float* __restrict__ hin) {
    int g = blockIdx.x;
    int c = threadIdx.x;  // 128
    int s = g_gstart[g], e = g_gstart[g + 1];
    float acc = 0.f;
    for (int i = s; i < e; i++) acc += hin[(size_t)i * 128 + c];
    int cnt = e - s;
    g_pool[g * 128 + c] = acc / (float)(cnt > 0 ? cnt : 1);
}
__global__ void k_fc(const float* __restrict__ w, const float* __restrict__ b,
                     float* __restrict__ out) {
    int g = blockIdx.x;
    __shared__ float sp[128];
    if (threadIdx.x < 128) sp[threadIdx.x] = g_pool[g * 128 + threadIdx.x];
    __syncthreads();
    int o = threadIdx.x;
    if (o < OUT_CH) {
        float acc = b[o];
#pragma unroll 8
        for (int k = 0; k < 128; k++) acc += sp[k] * w[k * OUT_CH + o];
        out[g * OUT_CH + o] = acc;
    }
}

// ---------------- driver ----------------
extern "C" void kernel_launch(void* const* d_in, const int* in_sizes, int n_in,
                              void* d_out, int out_size) {
    const float* x = (const float*)d_in[0];
    const int* ei = (const int*)d_in[1];       // int32! (jax x64 disabled downcasts int64)
    const int* batch = (const int*)d_in[2];    // int32
    const float* W1 = (const float*)d_in[3];
    const float* b1 = (const float*)d_in[6];
    const float* W2 = (const float*)d_in[7];
    const float* b2 = (const float*)d_in[10];
    const float* W3 = (const float*)d_in[11];
    const float* b3 = (const float*)d_in[14];
    const float* fcw = (const float*)d_in[15];
    const float* fcb = (const float*)d_in[16];
    float* out = (float*)d_out;

    // static scratch addresses (device-side symbols referenced directly in kernels;
    // here we only need h/hin pointers for kernel arguments)
    float* h;
    float* hin;
    cudaGetSymbolAddress((void**)&h, g_h);
    cudaGetSymbolAddress((void**)&hin, g_hin);

    const int* esrc = ei;
    const int* edst = ei + N_EDGES;
    const int N = N_NODES, E = N_EDGES;

    // --- CSR by dst (self loop at row start) ---
    k_init_counts<<<(N + 255) / 256, 256>>>();
    k_count_edges<<<(E + 255) / 256, 256>>>(edst);
    k_scan<<<1, 1024>>>();
    k_init_self<<<(N + 255) / 256, 256>>>();
    k_scatter<<<(E + 255) / 256, 256>>>(esrc, edst);

    // --- layer 1: 256 -> 4x128 ---
    k_sgemm<<<dim3(512 / 128, (N + 127) / 128), 256>>>(x, W1, h, N, 512, 256);
    k_alpha<<<(N * 4 * 32 + 255) / 256, 256>>>(h, (const float*)d_in[4], (const float*)d_in[5], N, 4);
    k_aggregate<4><<<N, 128>>>(h, b1, hin);

    // --- layer 2: 512 -> 4x128 ---
    k_sgemm<<<dim3(512 / 128, (N + 127) / 128), 256>>>(hin, W2, h, N, 512, 512);
    k_alpha<<<(N * 4 * 32 + 255) / 256, 256>>>(h, (const float*)d_in[8], (const float*)d_in[9], N, 4);
    k_aggregate<4><<<N, 128>>>(h, b2, hin);

    // --- layer 3: 512 -> 1x128 ---
    k_sgemm<<<dim3(128 / 128, (N + 127) / 128), 256>>>(hin, W3, h, N, 128, 512);
    k_alpha<<<(N * 1 * 32 + 255) / 256, 256>>>(h, (const float*)d_in[12], (const float*)d_in[13], N, 1);
    k_aggregate<1><<<N, 128>>>(h, b3, hin);

    // --- global mean pool + FC ---
    k_gbounds<<<1, 128>>>(batch);
    k_pool<<<NUM_GRAPHS, 128>>>(hin);
    k_fc<<<NUM_GRAPHS, 256>>>(fcw, fcb, out);
}

// round 8
// speedup vs baseline: 1.5806x; 1.5806x over previous
#include <cuda_runtime.h>
#include <cstdint>

#define N_NODES 20000
#define N_EDGES 320000
#define E_TOT   (N_EDGES + N_NODES)
#define NUM_GRAPHS 64
#define OUT_CH 200

// ---------------- scratch (static device globals; no runtime alloc) ------------
__device__ float g_h[(size_t)N_NODES * 512];    // GEMM output (per-layer transformed feats)
__device__ float g_hin[(size_t)N_NODES * 512];  // activated layer input / aggregate output
__device__ float g_as[(size_t)N_NODES * 4];
__device__ float g_ad[(size_t)N_NODES * 4];
__device__ int   g_rowp[N_NODES + 1];
__device__ int   g_cnt[N_NODES];
__device__ int   g_srcs[E_TOT];
__device__ float g_pool[NUM_GRAPHS * 128];
__device__ int   g_gstart[NUM_GRAPHS + 1];

// ---------------- helpers ----------------
__device__ __forceinline__ unsigned fenc(float f) {
    unsigned u = __float_as_uint(f);
    return (u & 0x80000000u) ? ~u : (u | 0x80000000u);
}
__device__ __forceinline__ float fdec(unsigned e) {
    unsigned u = (e & 0x80000000u) ? (e & 0x7fffffffu) : ~e;
    return __uint_as_float(u);
}

// ---------------- CSR build ----------------
__global__ void k_init_counts() {
    int i = blockIdx.x * blockDim.x + threadIdx.x;
    if (i < N_NODES) g_cnt[i] = 1;  // self loop
}
__global__ void k_count_edges(const int* __restrict__ dst) {
    int i = blockIdx.x * blockDim.x + threadIdx.x;
    if (i < N_EDGES) atomicAdd(&g_cnt[dst[i]], 1);
}
__global__ void k_scan() {
    __shared__ int part[1024];
    const int tid = threadIdx.x;
    const int n = N_NODES;
    const int CH = (n + 1023) / 1024;
    const int base = tid * CH;
    int s = 0;
    for (int i = 0; i < CH; i++) {
        int idx = base + i;
        if (idx < n) s += g_cnt[idx];
    }
    part[tid] = s;
    __syncthreads();
    for (int off = 1; off < 1024; off <<= 1) {
        int v = 0;
        if (tid >= off) v = part[tid - off];
        __syncthreads();
        if (tid >= off) part[tid] += v;
        __syncthreads();
    }
    int ex = (tid == 0) ? 0 : part[tid - 1];
    for (int i = 0; i < CH; i++) {
        int idx = base + i;
        if (idx < n) { g_rowp[idx] = ex; ex += g_cnt[idx]; }
    }
    if (tid == 1023) g_rowp[n] = part[1023];
}
__global__ void k_init_self() {
    int i = blockIdx.x * blockDim.x + threadIdx.x;
    if (i < N_NODES) {
        int r = g_rowp[i];
        g_srcs[r] = i;     // self loop first
        g_cnt[i] = r + 1;  // scatter cursor
    }
}
__global__ void k_scatter(const int* __restrict__ src, const int* __restrict__ dst) {
    int i = blockIdx.x * blockDim.x + threadIdx.x;
    if (i < N_EDGES) {
        int d = dst[i];
        int p = atomicAdd(&g_cnt[d], 1);
        g_srcs[p] = src[i];
    }
}

// ---------------- SGEMM: C[M,N] = A[M,K] @ B[K,N]; N%128==0, K%16==0 ----------------
__global__ __launch_bounds__(256) void k_sgemm(const float* __restrict__ A,
                                               const float* __restrict__ B,
                                               float* __restrict__ C,
                                               int M, int N, int K) {
    constexpr int BM = 128, BN = 128, BK = 16, TM = 8, TN = 8;
    __shared__ float As[BK][BM];
    __shared__ float Bs[BK][BN];
    const int tid = threadIdx.x;
    const int tr = tid / 16;
    const int tc = tid % 16;
    const int row0 = blockIdx.y * BM;
    const int col0 = blockIdx.x * BN;

    const int ar = tid / 4;          // 0..63
    const int ac = (tid % 4) * 4;    // 0,4,8,12
    const int br = tid / 32;         // 0..7
    const int bc = (tid % 32) * 4;   // 0..124

    float acc[TM][TN];
#pragma unroll
    for (int i = 0; i < TM; i++)
#pragma unroll
        for (int j = 0; j < TN; j++) acc[i][j] = 0.f;

    for (int k0 = 0; k0 < K; k0 += BK) {
#pragma unroll
        for (int i = 0; i < 2; i++) {
            int r = row0 + ar + i * 64;
            float4 v = make_float4(0.f, 0.f, 0.f, 0.f);
            if (r < M) v = *(const float4*)(A + (size_t)r * K + k0 + ac);
            As[ac + 0][ar + i * 64] = v.x;
            As[ac + 1][ar + i * 64] = v.y;
            As[ac + 2][ar + i * 64] = v.z;
            As[ac + 3][ar + i * 64] = v.w;
        }
#pragma unroll
        for (int i = 0; i < 2; i++) {
            int r = k0 + br + i * 8;
            *(float4*)&Bs[br + i * 8][bc] = *(const float4*)(B + (size_t)r * N + col0 + bc);
        }
        __syncthreads();
#pragma unroll
        for (int kk = 0; kk < BK; kk++) {
            float a[TM], b[TN];
#pragma unroll
            for (int i = 0; i < TM; i++) a[i] = As[kk][tr * TM + i];
#pragma unroll
            for (int j = 0; j < TN; j++) b[j] = Bs[kk][tc * TN + j];
#pragma unroll
            for (int i = 0; i < TM; i++)
#pragma unroll
                for (int j = 0; j < TN; j++) acc[i][j] += a[i] * b[j];
        }
        __syncthreads();
    }
#pragma unroll
    for (int i = 0; i < TM; i++) {
        int r = row0 + tr * TM + i;
        if (r < M) {
#pragma unroll
            for (int j = 0; j < TN; j += 4) {
                *(float4*)(C + (size_t)r * N + col0 + tc * TN + j) =
                    make_float4(acc[i][j], acc[i][j + 1], acc[i][j + 2], acc[i][j + 3]);
            }
        }
    }
}

// ---------------- alpha_s / alpha_d : one warp per (node, head), C=128 ----------------
__global__ void k_alpha(const float* __restrict__ h, const float* __restrict__ a_src,
                        const float* __restrict__ a_dst, int N, int H) {
    int w = (blockIdx.x * blockDim.x + threadIdx.x) >> 5;
    int lane = threadIdx.x & 31;
    if (w >= N * H) return;
    int n = w / H, hd = w % H;
    const float* hp = h + (size_t)n * H * 128 + hd * 128;
    float4 v = *(const float4*)(hp + lane * 4);
    float4 s = *(const float4*)(a_src + hd * 128 + lane * 4);
    float4 d = *(const float4*)(a_dst + hd * 128 + lane * 4);
    float ss = v.x * s.x + v.y * s.y + v.z * s.z + v.w * s.w;
    float dd = v.x * d.x + v.y * d.y + v.z * d.z + v.w * d.w;
#pragma unroll
    for (int o = 16; o; o >>= 1) {
        ss += __shfl_down_sync(0xffffffffu, ss, o);
        dd += __shfl_down_sync(0xffffffffu, dd, o);
    }
    if (lane == 0) { g_as[w] = ss; g_ad[w] = dd; }
}

// ---------------- per-node softmax + weighted aggregation (block per node) ----------------
template <int H>
__global__ __launch_bounds__(128) void k_aggregate(
    const float* __restrict__ hft,   // [N, H*128]
    const float* __restrict__ bias, float* __restrict__ out) {
    constexpr int OUTD = H * 128;
    constexpr int CPT = OUTD / 128;   // channels per thread
    const int n = blockIdx.x;
    const int tid = threadIdx.x;
    const int r0 = g_rowp[n];
    const int deg = g_rowp[n + 1] - r0;

    __shared__ unsigned s_maxe[H];
    __shared__ float s_sum[H];
    __shared__ float s_adv[H];
    __shared__ float s_m[H];
    __shared__ float s_den[H];
    __shared__ float s_w[64 * H];
    __shared__ int s_src[64];

    if (tid < H) {
        s_maxe[tid] = 0u;
        s_sum[tid] = 0.f;
        s_adv[tid] = g_ad[(size_t)n * H + tid];
    }
    __syncthreads();

    // phase 1: per-head max of leaky_relu(as[src]+ad[n])
    {
        float lm[H];
#pragma unroll
        for (int h = 0; h < H; h++) lm[h] = -3.0e38f;
        for (int j = tid; j < deg; j += 128) {
            int s = g_srcs[r0 + j];
#pragma unroll
            for (int h = 0; h < H; h++) {
                float e = g_as[(size_t)s * H + h] + s_adv[h];
                e = e > 0.f ? e : 0.2f * e;
                lm[h] = fmaxf(lm[h], e);
            }
        }
#pragma unroll
        for (int h = 0; h < H; h++) atomicMax(&s_maxe[h], fenc(lm[h]));
    }
    __syncthreads();
    if (tid < H) s_m[tid] = fdec(s_maxe[tid]);
    __syncthreads();

    // phase 2: per-head sum of exp(e - m)
    {
        float ls[H];
#pragma unroll
        for (int h = 0; h < H; h++) ls[h] = 0.f;
        for (int j = tid; j < deg; j += 128) {
            int s = g_srcs[r0 + j];
#pragma unroll
            for (int h = 0; h < H; h++) {
                float e = g_as[(size_t)s * H + h] + s_adv[h];
                e = e > 0.f ? e : 0.2f * e;
                ls[h] += expf(e - s_m[h]);
            }
        }
#pragma unroll
        for (int h = 0; h < H; h++)
            if (ls[h] != 0.f) atomicAdd(&s_sum[h], ls[h]);
    }
    __syncthreads();
    if (tid < H) s_den[tid] = s_sum[tid] + 1e-16f;
    __syncthreads();

    // phase 3: chunked weighted gather of h[src]
    const int c0 = tid * CPT;
    const int myh = c0 >> 7;
    float acc[CPT];
#pragma unroll
    for (int i = 0; i < CPT; i++) acc[i] = 0.f;

    for (int base = 0; base < deg; base += 64) {
        int cn = min(64, deg - base);
        __syncthreads();
        if (tid < cn) {
            int s = g_srcs[r0 + base + tid];
            s_src[tid] = s;
#pragma unroll
            for (int h = 0; h < H; h++) {
                float e = g_as[(size_t)s * H + h] + s_adv[h];
                e = e > 0.f ? e : 0.2f * e;
                s_w[tid * H + h] = expf(e - s_m[h]) / s_den[h];
            }
        }
        __syncthreads();
        for (int j = 0; j < cn; j++) {
            int s = s_src[j];
            float coef = s_w[j * H + myh];
            const float* hp = hft + (size_t)s * OUTD + c0;
            if (CPT == 4) {
                float4 v = *(const float4*)hp;
                acc[0] += coef * v.x;
                acc[1] += coef * v.y;
                acc[2] += coef * v.z;
                acc[3] += coef * v.w;
            } else {
                acc[0] += coef * hp[0];
            }
        }
    }
#pragma unroll
    for (int i = 0; i < CPT; i++) {
        float v = acc[i] + bias[c0 + i];
        v = v > 0.f ? v : expm1f(v);   // ELU
        out[(size_t)n * OUTD + c0 + i] = v;
    }
}

// ---------------- pooling / FC ----------------
__global__ void k_gbounds(const int* __restrict__ batch) {
    int g = blockIdx.x * blockDim.x + threadIdx.x;
    const int N = N_NODES, G = NUM_GRAPHS;
    if (g > G) return;
    if (g == G) { g_gstart[G] = N; return; }
    int lo = 0, hi = N;
    while (lo < hi) {
        int mid = (lo + hi) >> 1;
        if (batch[mid] < g) lo = mid + 1;
        else hi = mid;
    }
    g_gstart[g] = lo;
}
__global__ void k_pool(const float* __restrict__ hin) {
    int g = blockIdx.x;
    int c = threadIdx.x;  // 128
    int s = g_gstart[g], e = g_gstart[g + 1];
    float acc = 0.f;
    for (int i = s; i < e; i++) acc += hin[(size_t)i * 128 + c];
    int cnt = e - s;
    g_pool[g * 128 + c] = acc / (float)(cnt > 0 ? cnt : 1);
}
__global__ void k_fc(const float* __restrict__ w, const float* __restrict__ b,
                     float* __restrict__ out) {
    int g = blockIdx.x;
    __shared__ float sp[128];
    if (threadIdx.x < 128) sp[threadIdx.x] = g_pool[g * 128 + threadIdx.x];
    __syncthreads();
    int o = threadIdx.x;
    if (o < OUT_CH) {
        float acc = b[o];
#pragma unroll 8
        for (int k = 0; k < 128; k++) acc += sp[k] * w[k * OUT_CH + o];
        out[g * OUT_CH + o] = acc;
    }
}

// ---------------- driver ----------------
extern "C" void kernel_launch(void* const* d_in, const int* in_sizes, int n_in,
                              void* d_out, int out_size) {
    const float* x = (const float*)d_in[0];
    const int* ei = (const int*)d_in[1];       // int32! (jax x64 disabled downcasts int64)
    const int* batch = (const int*)d_in[2];    // int32
    const float* W1 = (const float*)d_in[3];
    const float* b1 = (const float*)d_in[6];
    const float* W2 = (const float*)d_in[7];
    const float* b2 = (const float*)d_in[10];
    const float* W3 = (const float*)d_in[11];
    const float* b3 = (const float*)d_in[14];
    const float* fcw = (const float*)d_in[15];
    const float* fcb = (const float*)d_in[16];
    float* out = (float*)d_out;

    // static scratch addresses (device-side symbols referenced directly in kernels;
    // here we only need h/hin pointers for kernel arguments)
    float* h;
    float* hin;
    cudaGetSymbolAddress((void**)&h, g_h);
    cudaGetSymbolAddress((void**)&hin, g_hin);

    const int* esrc = ei;
    const int* edst = ei + N_EDGES;
    const int N = N_NODES, E = N_EDGES;

    // --- CSR by dst (self loop at row start) ---
    k_init_counts<<<(N + 255) / 256, 256>>>();
    k_count_edges<<<(E + 255) / 256, 256>>>(edst);
    k_scan<<<1, 1024>>>();
    k_init_self<<<(N + 255) / 256, 256>>>();
    k_scatter<<<(E + 255) / 256, 256>>>(esrc, edst);

    // --- layer 1: 256 -> 4x128 ---
    k_sgemm<<<dim3(512 / 128, (N + 127) / 128), 256>>>(x, W1, h, N, 512, 256);
    k_alpha<<<(N * 4 * 32 + 255) / 256, 256>>>(h, (const float*)d_in[4], (const float*)d_in[5], N, 4);
    k_aggregate<4><<<N, 128>>>(h, b1, hin);

    // --- layer 2: 512 -> 4x128 ---
    k_sgemm<<<dim3(512 / 128, (N + 127) / 128), 256>>>(hin, W2, h, N, 512, 512);
    k_alpha<<<(N * 4 * 32 + 255) / 256, 256>>>(h, (const float*)d_in[8], (const float*)d_in[9], N, 4);
    k_aggregate<4><<<N, 128>>>(h, b2, hin);

    // --- layer 3: 512 -> 1x128 ---
    k_sgemm<<<dim3(128 / 128, (N + 127) / 128), 256>>>(hin, W3, h, N, 128, 512);
    k_alpha<<<(N * 1 * 32 + 255) / 256, 256>>>(h, (const float*)d_in[12], (const float*)d_in[13], N, 1);
    k_aggregate<1><<<N, 128>>>(h, b3, hin);

    // --- global mean pool + FC ---
    k_gbounds<<<1, 128>>>(batch);
    k_pool<<<NUM_GRAPHS, 128>>>(hin);
    k_fc<<<NUM_GRAPHS, 256>>>(fcw, fcb, out);
}

// round 13
// speedup vs baseline: 2.3011x; 1.4558x over previous
#include <cuda_runtime.h>
#include <cstdint>

#define N_NODES 20000
#define N_EDGES 320000
#define E_TOT   (N_EDGES + N_NODES)
#define NUM_GRAPHS 64
#define OUT_CH 200

// ---------------- scratch (static device globals; no runtime alloc) ------------
__device__ float g_h[(size_t)N_NODES * 512];
__device__ float g_hin[(size_t)N_NODES * 512];
__device__ float g_as[(size_t)N_NODES * 4];
__device__ float g_ad[(size_t)N_NODES * 4];
__device__ int   g_rowp[N_NODES + 1];
__device__ int   g_cnt[N_NODES];
__device__ int   g_srcs[E_TOT];
__device__ float g_pool[NUM_GRAPHS * 128];
__device__ int   g_gstart[NUM_GRAPHS + 1];

// ---------------- helpers ----------------
__device__ __forceinline__ unsigned fenc(float f) {
    unsigned u = __float_as_uint(f);
    return (u & 0x80000000u) ? ~u : (u | 0x80000000u);
}
__device__ __forceinline__ float fdec(unsigned e) {
    unsigned u = (e & 0x80000000u) ? (e & 0x7fffffffu) : ~e;
    return __uint_as_float(u);
}
__device__ __forceinline__ uint32_t f2tf32(float f) {
    uint32_t o;
    asm("cvt.rna.tf32.f32 %0, %1;" : "=r"(o) : "f"(f));
    return o;
}

// ---------------- CSR build ----------------
__global__ void k_init_counts() {
    int i = blockIdx.x * blockDim.x + threadIdx.x;
    if (i < N_NODES) g_cnt[i] = 1;  // self loop
}
__global__ void k_count_edges(const int* __restrict__ dst) {
    int i = blockIdx.x * blockDim.x + threadIdx.x;
    if (i < N_EDGES) atomicAdd(&g_cnt[dst[i]], 1);
}
__global__ void k_scan() {
    __shared__ int part[1024];
    const int tid = threadIdx.x;
    const int n = N_NODES;
    const int CH = (n + 1023) / 1024;
    const int base = tid * CH;
    int s = 0;
    for (int i = 0; i < CH; i++) {
        int idx = base + i;
        if (idx < n) s += g_cnt[idx];
    }
    part[tid] = s;
    __syncthreads();
    for (int off = 1; off < 1024; off <<= 1) {
        int v = 0;
        if (tid >= off) v = part[tid - off];
        __syncthreads();
        if (tid >= off) part[tid] += v;
        __syncthreads();
    }
    int ex = (tid == 0) ? 0 : part[tid - 1];
    for (int i = 0; i < CH; i++) {
        int idx = base + i;
        if (idx < n) { g_rowp[idx] = ex; ex += g_cnt[idx]; }
    }
    if (tid == 1023) g_rowp[n] = part[1023];
}
__global__ void k_init_self() {
    int i = blockIdx.x * blockDim.x + threadIdx.x;
    if (i < N_NODES) {
        int r = g_rowp[i];
        g_srcs[r] = i;
        g_cnt[i] = r + 1;
    }
}
__global__ void k_scatter(const int* __restrict__ src, const int* __restrict__ dst) {
    int i = blockIdx.x * blockDim.x + threadIdx.x;
    if (i < N_EDGES) {
        int d = dst[i];
        int p = atomicAdd(&g_cnt[d], 1);
        g_srcs[p] = src[i];
    }
}

// ---------------- TF32 tensor-core GEMM: C[M,N] = A[M,K] @ B[K,N] ----------------
// BM=128, BN=128, BK=16, 8 warps as 4x2, each warp does 32x64 via m16n8k8 mma.
__global__ __launch_bounds__(256) void k_mma_gemm(const float* __restrict__ A,
                                                  const float* __restrict__ B,
                                                  float* __restrict__ C,
                                                  int M, int N, int K) {
    constexpr int BM = 128, BN = 128, BK = 16;
    __shared__ uint32_t As[BK][BM + 4];
    __shared__ uint32_t Bs[BK][BN + 4];

    const int tid = threadIdx.x;
    const int warp = tid >> 5;
    const int lane = tid & 31;
    const int wr = warp >> 1;          // 0..3  (warp row)
    const int wc = warp & 1;           // 0..1  (warp col)
    const int gid = lane >> 2;         // 0..7
    const int tig = lane & 3;          // 0..3

    const int row0 = blockIdx.y * BM;
    const int col0 = blockIdx.x * BN;

    // global->smem indices
    const int ar = tid >> 2;           // 0..63 (A row within tile)
    const int ac = (tid & 3) * 4;      // 0,4,8,12 (A k-col)
    const int br = tid >> 5;           // 0..7  (B k-row)
    const int bc = (tid & 31) * 4;     // 0..124 (B n-col)

    float acc[2][8][4];
#pragma unroll
    for (int mi = 0; mi < 2; mi++)
#pragma unroll
        for (int ni = 0; ni < 8; ni++)
#pragma unroll
            for (int c = 0; c < 4; c++) acc[mi][ni][c] = 0.f;

    for (int k0 = 0; k0 < K; k0 += BK) {
        // load A tile (rows ar, ar+64), convert to tf32
#pragma unroll
        for (int i = 0; i < 2; i++) {
            int r = row0 + ar + i * 64;
            float4 v = make_float4(0.f, 0.f, 0.f, 0.f);
            if (r < M) v = *(const float4*)(A + (size_t)r * K + k0 + ac);
            As[ac + 0][ar + i * 64] = f2tf32(v.x);
            As[ac + 1][ar + i * 64] = f2tf32(v.y);
            As[ac + 2][ar + i * 64] = f2tf32(v.z);
            As[ac + 3][ar + i * 64] = f2tf32(v.w);
        }
        // load B tile (k rows br, br+8)
#pragma unroll
        for (int i = 0; i < 2; i++) {
            int r = k0 + br + i * 8;
            float4 v = *(const float4*)(B + (size_t)r * N + col0 + bc);
            Bs[br + i * 8][bc + 0] = f2tf32(v.x);
            Bs[br + i * 8][bc + 1] = f2tf32(v.y);
            Bs[br + i * 8][bc + 2] = f2tf32(v.z);
            Bs[br + i * 8][bc + 3] = f2tf32(v.w);
        }
        __syncthreads();

#pragma unroll
        for (int kk = 0; kk < BK; kk += 8) {
            uint32_t af[2][4];
#pragma unroll
            for (int mi = 0; mi < 2; mi++) {
                int r = wr * 32 + mi * 16 + gid;
                af[mi][0] = As[kk + tig][r];
                af[mi][1] = As[kk + tig][r + 8];
                af[mi][2] = As[kk + tig + 4][r];
                af[mi][3] = As[kk + tig + 4][r + 8];
            }
            uint32_t bf[8][2];
#pragma unroll
            for (int ni = 0; ni < 8; ni++) {
                int c = wc * 64 + ni * 8 + gid;
                bf[ni][0] = Bs[kk + tig][c];
                bf[ni][1] = Bs[kk + tig + 4][c];
            }
#pragma unroll
            for (int mi = 0; mi < 2; mi++)
#pragma unroll
                for (int ni = 0; ni < 8; ni++) {
                    asm volatile(
                        "mma.sync.aligned.m16n8k8.row.col.f32.tf32.tf32.f32 "
                        "{%0,%1,%2,%3}, {%4,%5,%6,%7}, {%8,%9}, {%0,%1,%2,%3};"
                        : "+f"(acc[mi][ni][0]), "+f"(acc[mi][ni][1]),
                          "+f"(acc[mi][ni][2]), "+f"(acc[mi][ni][3])
                        : "r"(af[mi][0]), "r"(af[mi][1]), "r"(af[mi][2]), "r"(af[mi][3]),
                          "r"(bf[ni][0]), "r"(bf[ni][1]));
                }
        }
        __syncthreads();
    }

    // store C
#pragma unroll
    for (int mi = 0; mi < 2; mi++) {
        int rbase = row0 + wr * 32 + mi * 16 + gid;
#pragma unroll
        for (int ni = 0; ni < 8; ni++) {
            int c = col0 + wc * 64 + ni * 8 + tig * 2;
            if (rbase < M)
                *(float2*)(C + (size_t)rbase * N + c) =
                    make_float2(acc[mi][ni][0], acc[mi][ni][1]);
            if (rbase + 8 < M)
                *(float2*)(C + (size_t)(rbase + 8) * N + c) =
                    make_float2(acc[mi][ni][2], acc[mi][ni][3]);
        }
    }
}

// ---------------- alpha_s / alpha_d : one warp per (node, head), C=128 ----------------
__global__ void k_alpha(const float* __restrict__ h, const float* __restrict__ a_src,
                        const float* __restrict__ a_dst, int N, int H) {
    int w = (blockIdx.x * blockDim.x + threadIdx.x) >> 5;
    int lane = threadIdx.x & 31;
    if (w >= N * H) return;
    int n = w / H, hd = w % H;
    const float* hp = h + (size_t)n * H * 128 + hd * 128;
    float4 v = *(const float4*)(hp + lane * 4);
    float4 s = *(const float4*)(a_src + hd * 128 + lane * 4);
    float4 d = *(const float4*)(a_dst + hd * 128 + lane * 4);
    float ss = v.x * s.x + v.y * s.y + v.z * s.z + v.w * s.w;
    float dd = v.x * d.x + v.y * d.y + v.z * d.z + v.w * d.w;
#pragma unroll
    for (int o = 16; o; o >>= 1) {
        ss += __shfl_down_sync(0xffffffffu, ss, o);
        dd += __shfl_down_sync(0xffffffffu, dd, o);
    }
    if (lane == 0) { g_as[w] = ss; g_ad[w] = dd; }
}

// ---------------- per-node softmax + weighted aggregation (block per node) ----------------
template <int H>
__global__ __launch_bounds__(128) void k_aggregate(
    const float* __restrict__ hft, const float* __restrict__ bias,
    float* __restrict__ out) {
    constexpr int OUTD = H * 128;
    constexpr int CPT = OUTD / 128;
    const int n = blockIdx.x;
    const int tid = threadIdx.x;
    const int r0 = g_rowp[n];
    const int deg = g_rowp[n + 1] - r0;

    __shared__ unsigned s_maxe[H];
    __shared__ float s_sum[H];
    __shared__ float s_adv[H];
    __shared__ float s_m[H];
    __shared__ float s_den[H];
    __shared__ float s_w[64 * H];
    __shared__ int s_src[64];

    if (tid < H) {
        s_maxe[tid] = 0u;
        s_sum[tid] = 0.f;
        s_adv[tid] = g_ad[(size_t)n * H + tid];
    }
    __syncthreads();

    {
        float lm[H];
#pragma unroll
        for (int h = 0; h < H; h++) lm[h] = -3.0e38f;
        for (int j = tid; j < deg; j += 128) {
            int s = g_srcs[r0 + j];
#pragma unroll
            for (int h = 0; h < H; h++) {
                float e = g_as[(size_t)s * H + h] + s_adv[h];
                e = e > 0.f ? e : 0.2f * e;
                lm[h] = fmaxf(lm[h], e);
            }
        }
#pragma unroll
        for (int h = 0; h < H; h++) atomicMax(&s_maxe[h], fenc(lm[h]));
    }
    __syncthreads();
    if (tid < H) s_m[tid] = fdec(s_maxe[tid]);
    __syncthreads();

    {
        float ls[H];
#pragma unroll
        for (int h = 0; h < H; h++) ls[h] = 0.f;
        for (int j = tid; j < deg; j += 128) {
            int s = g_srcs[r0 + j];
#pragma unroll
            for (int h = 0; h < H; h++) {
                float e = g_as[(size_t)s * H + h] + s_adv[h];
                e = e > 0.f ? e : 0.2f * e;
                ls[h] += expf(e - s_m[h]);
            }
        }
#pragma unroll
        for (int h = 0; h < H; h++)
            if (ls[h] != 0.f) atomicAdd(&s_sum[h], ls[h]);
    }
    __syncthreads();
    if (tid < H) s_den[tid] = s_sum[tid] + 1e-16f;
    __syncthreads();

    const int c0 = tid * CPT;
    const int myh = c0 >> 7;
    float acc[CPT];
#pragma unroll
    for (int i = 0; i < CPT; i++) acc[i] = 0.f;

    for (int base = 0; base < deg; base += 64) {
        int cn = min(64, deg - base);
        __syncthreads();
        if (tid < cn) {
            int s = g_srcs[r0 + base + tid];
            s_src[tid] = s;
#pragma unroll
            for (int h = 0; h < H; h++) {
                float e = g_as[(size_t)s * H + h] + s_adv[h];
                e = e > 0.f ? e : 0.2f * e;
                s_w[tid * H + h] = expf(e - s_m[h]) / s_den[h];
            }
        }
        __syncthreads();
        for (int j = 0; j < cn; j++) {
            int s = s_src[j];
            float coef = s_w[j * H + myh];
            const float* hp = hft + (size_t)s * OUTD + c0;
            if (CPT == 4) {
                float4 v = *(const float4*)hp;
                acc[0] += coef * v.x;
                acc[1] += coef * v.y;
                acc[2] += coef * v.z;
                acc[3] += coef * v.w;
            } else {
                acc[0] += coef * hp[0];
            }
        }
    }
#pragma unroll
    for (int i = 0; i < CPT; i++) {
        float v = acc[i] + bias[c0 + i];
        v = v > 0.f ? v : expm1f(v);   // ELU
        out[(size_t)n * OUTD + c0 + i] = v;
    }
}

// ---------------- pooling / FC ----------------
__global__ void k_gbounds(const int* __restrict__ batch) {
    int g = blockIdx.x * blockDim.x + threadIdx.x;
    const int N = N_NODES, G = NUM_GRAPHS;
    if (g > G) return;
    if (g == G) { g_gstart[G] = N; return; }
    int lo = 0, hi = N;
    while (lo < hi) {
        int mid = (lo + hi) >> 1;
        if (batch[mid] < g) lo = mid + 1;
        else hi = mid;
    }
    g_gstart[g] = lo;
}
__global__ void k_pool(const float* __restrict__ hin) {
    int g = blockIdx.x;
    int c = threadIdx.x;
    int s = g_gstart[g], e = g_gstart[g + 1];
    float acc = 0.f;
    for (int i = s; i < e; i++) acc += hin[(size_t)i * 128 + c];
    int cnt = e - s;
    g_pool[g * 128 + c] = acc / (float)(cnt > 0 ? cnt : 1);
}
__global__ void k_fc(const float* __restrict__ w, const float* __restrict__ b,
                     float* __restrict__ out) {
    int g = blockIdx.x;
    __shared__ float sp[128];
    if (threadIdx.x < 128) sp[threadIdx.x] = g_pool[g * 128 + threadIdx.x];
    __syncthreads();
    int o = threadIdx.x;
    if (o < OUT_CH) {
        float acc = b[o];
#pragma unroll 8
        for (int k = 0; k < 128; k++) acc += sp[k] * w[k * OUT_CH + o];
        out[g * OUT_CH + o] = acc;
    }
}

// ---------------- driver ----------------
extern "C" void kernel_launch(void* const* d_in, const int* in_sizes, int n_in,
                              void* d_out, int out_size) {
    const float* x = (const float*)d_in[0];
    const int* ei = (const int*)d_in[1];       // int32 (jax x64 disabled)
    const int* batch = (const int*)d_in[2];
    const float* W1 = (const float*)d_in[3];
    const float* b1 = (const float*)d_in[6];
    const float* W2 = (const float*)d_in[7];
    const float* b2 = (const float*)d_in[10];
    const float* W3 = (const float*)d_in[11];
    const float* b3 = (const float*)d_in[14];
    const float* fcw = (const float*)d_in[15];
    const float* fcb = (const float*)d_in[16];
    float* out = (float*)d_out;

    float* h;
    float* hin;
    cudaGetSymbolAddress((void**)&h, g_h);
    cudaGetSymbolAddress((void**)&hin, g_hin);

    const int* esrc = ei;
    const int* edst = ei + N_EDGES;
    const int N = N_NODES, E = N_EDGES;

    // --- CSR by dst (self loop at row start) ---
    k_init_counts<<<(N + 255) / 256, 256>>>();
    k_count_edges<<<(E + 255) / 256, 256>>>(edst);
    k_scan<<<1, 1024>>>();
    k_init_self<<<(N + 255) / 256, 256>>>();
    k_scatter<<<(E + 255) / 256, 256>>>(esrc, edst);

    const int MB = (N + 127) / 128;

    // --- layer 1: 256 -> 4x128 ---
    k_mma_gemm<<<dim3(4, MB), 256>>>(x, W1, h, N, 512, 256);
    k_alpha<<<(N * 4 * 32 + 255) / 256, 256>>>(h, (const float*)d_in[4], (const float*)d_in[5], N, 4);
    k_aggregate<4><<<N, 128>>>(h, b1, hin);

    // --- layer 2: 512 -> 4x128 ---
    k_mma_gemm<<<dim3(4, MB), 256>>>(hin, W2, h, N, 512, 512);
    k_alpha<<<(N * 4 * 32 + 255) / 256, 256>>>(h, (const float*)d_in[8], (const float*)d_in[9], N, 4);
    k_aggregate<4><<<N, 128>>>(h, b2, hin);

    // --- layer 3: 512 -> 1x128 ---
    k_mma_gemm<<<dim3(1, MB), 256>>>(hin, W3, h, N, 128, 512);
    k_alpha<<<(N * 1 * 32 + 255) / 256, 256>>>(h, (const float*)d_in[12], (const float*)d_in[13], N, 1);
    k_aggregate<1><<<N, 128>>>(h, b3, hin);

    // --- global mean pool + FC ---
    k_gbounds<<<1, 128>>>(batch);
    k_pool<<<NUM_GRAPHS, 128>>>(hin);
    k_fc<<<NUM_GRAPHS, 256>>>(fcw, fcb, out);
}